// round 15
// baseline (speedup 1.0000x reference)
#include <cuda_runtime.h>
#include <cuda_fp16.h>
#include <cstdint>

// B=1, H=128, S=256, D=2048, fp32 in/out.
#define HH 128
#define SS 256
#define DD 2048

// ---------------------------------------------------------------------------
// Device scratch (no allocs allowed anywhere).
// ---------------------------------------------------------------------------
__device__ __half g_phi[(size_t)HH * SS * SS];    // P fp16 [h,q,s]
__device__ int    g_flag[HH];                      // per-head completion count

// ---------------------------------------------------------------------------
// Helpers
// ---------------------------------------------------------------------------
__device__ __forceinline__ uint32_t smem_to_u32(const void* p) {
  uint32_t a;
  asm("{ .reg .u64 t; cvta.to.shared.u64 t, %1; cvt.u32.u64 %0, t; }" : "=r"(a) : "l"(p));
  return a;
}
#define SWZ(o) ((o) ^ (((o) >> 3) & 0x70))

__device__ __forceinline__ void cp_async16(uint32_t dst, const void* src) {
  asm volatile("cp.async.cg.shared.global [%0], [%1], 16;" :: "r"(dst), "l"(src) : "memory");
}
__device__ __forceinline__ void cp_commit() {
  asm volatile("cp.async.commit_group;" ::: "memory");
}
__device__ __forceinline__ void cp_wait0() {
  asm volatile("cp.async.wait_group 0;" ::: "memory");
}
__device__ __forceinline__ void cp_wait1() {
  asm volatile("cp.async.wait_group 1;" ::: "memory");
}
__device__ __forceinline__ void cp_wait2() {
  asm volatile("cp.async.wait_group 2;" ::: "memory");
}

__device__ __forceinline__ void ldsm_x4(uint32_t addr, uint32_t* r) {
  asm volatile("ldmatrix.sync.aligned.m8n8.x4.shared.b16 {%0,%1,%2,%3}, [%4];"
               : "=r"(r[0]), "=r"(r[1]), "=r"(r[2]), "=r"(r[3]) : "r"(addr));
}
__device__ __forceinline__ void ldsm_x4_t(uint32_t addr, uint32_t* r) {
  asm volatile("ldmatrix.sync.aligned.m8n8.x4.trans.shared.b16 {%0,%1,%2,%3}, [%4];"
               : "=r"(r[0]), "=r"(r[1]), "=r"(r[2]), "=r"(r[3]) : "r"(addr));
}

__device__ __forceinline__ void mma16816(float* c, const uint32_t* a, const uint32_t* b) {
  asm volatile(
      "mma.sync.aligned.m16n8k16.row.col.f32.f16.f16.f32 "
      "{%0,%1,%2,%3}, {%4,%5,%6,%7}, {%8,%9}, {%0,%1,%2,%3};"
      : "+f"(c[0]), "+f"(c[1]), "+f"(c[2]), "+f"(c[3])
      : "r"(a[0]), "r"(a[1]), "r"(a[2]), "r"(a[3]), "r"(b[0]), "r"(b[1]));
}

__device__ __forceinline__ void sts8h(uint32_t addr, __half a, __half b,
                                      __half c, __half d) {
  __half2 p0(a, b), p1(c, d);
  asm volatile("st.shared.v2.b32 [%0], {%1, %2};" ::
               "r"(addr), "r"(*(uint32_t*)&p0), "r"(*(uint32_t*)&p1) : "memory");
}

// Window tile rows: 128B hold 64 k fp16 = two 32-k chunks; p = chunk parity
// selects the 64B half; ks = 16-k step within chunk. SW128 swizzled.
__device__ __forceinline__ uint32_t a_frag_addr(uint32_t tb, int mt, int ks, int p, int lid) {
  uint32_t off = (uint32_t)(mt + (lid & 15)) * 128 + p * 64 + ks * 32 + ((lid >> 4) * 16);
  return tb + SWZ(off);
}
__device__ __forceinline__ uint32_t b_frag_addr(uint32_t tb, int nt, int ks, int p, int lid) {
  uint32_t off = (uint32_t)(nt + ((lid >> 4) & 1) * 8 + (lid & 7)) * 128
               + p * 64 + ks * 32 + (((lid >> 3) & 1) * 16);
  return tb + SWZ(off);
}
// V trans window: per 64-d half 8KB: 64 s-rows (two chunks) x 128B (64 d fp16).
__device__ __forceinline__ uint32_t v_frag_addr(uint32_t tvw, int half, int nt,
                                                int ks, int ckp, int lid) {
  uint32_t base = tvw + (uint32_t)half * 8192u;
  uint32_t row = (uint32_t)(ckp * 32 + ks * 16 + ((lid >> 3) & 1) * 8 + (lid & 7));
  uint32_t col = (uint32_t)(nt + ((lid >> 4) & 1) * 8) * 2;
  return base + SWZ(row * 128 + col);
}

// ---------------------------------------------------------------------------
// JAX threefry2x32 (20 rounds) — exact; partitionable counter layout.
// ---------------------------------------------------------------------------
__device__ __forceinline__ uint32_t rotl32(uint32_t x, int r) {
  return (x << r) | (x >> (32 - r));
}
__device__ __forceinline__ void threefry2x32(uint32_t k0, uint32_t k1,
                                             uint32_t& x0, uint32_t& x1) {
  const uint32_t ks0 = k0, ks1 = k1, ks2 = k0 ^ k1 ^ 0x1BD11BDAu;
  x0 += ks0; x1 += ks1;
#define TF_R(r) { x0 += x1; x1 = rotl32(x1, r); x1 ^= x0; }
  TF_R(13) TF_R(15) TF_R(26) TF_R(6)
  x0 += ks1; x1 += ks2 + 1u;
  TF_R(17) TF_R(29) TF_R(16) TF_R(24)
  x0 += ks2; x1 += ks0 + 2u;
  TF_R(13) TF_R(15) TF_R(26) TF_R(6)
  x0 += ks0; x1 += ks1 + 3u;
  TF_R(17) TF_R(29) TF_R(16) TF_R(24)
  x0 += ks1; x1 += ks2 + 4u;
  TF_R(13) TF_R(15) TF_R(26) TF_R(6)
  x0 += ks2; x1 += ks0 + 5u;
#undef TF_R
}
__device__ __forceinline__ bool keep_draw(uint32_t i) {
  uint32_t x0 = 0u, x1 = i;
  threefry2x32(0u, 42u, x0, x1);
  const uint32_t bits = x0 ^ x1;
  const float u = __uint_as_float((bits >> 9) | 0x3F800000u) - 1.0f;
  return u < 0.1f;
}

// ===========================================================================
// Shared smem maps (per-CTA, 192KB launch smem).
// qks part: QF(0..2) 3x48KB @0 ; QAW 16KB @147456 ; QBW 32KB @163840.
// pv  part: PW(0..3) P resident 4x32KB @0 ; VF(0..1) 2x16KB @131072 ;
//           VT 16KB @163840.
// ===========================================================================
#define QF(s) (sbase + (uint32_t)(s) * 49152u)
#define QAW   (sbase + 147456u)
#define QBW   (sbase + 163840u)
#define PW(k) (sbase + (uint32_t)(k) * 32768u)
#define VF(s) (sbase + 131072u + (uint32_t)(s) * 16384u)
#define VTW   (sbase + 163840u)
#define MEGA_SMEM 196608

__device__ __forceinline__ void qks_cp(
    uint32_t fbase, const float* __restrict__ Qf, const float* __restrict__ Kf,
    size_t qrow0, size_t krow0, int kb, int tid) {
#pragma unroll
  for (int i = 0; i < 6; i++) {
    int seg = tid + i * 512;            // 0..3071 : 1024 A + 2048 B
    int tile = (seg >= 1024);
    int w = tile ? seg - 1024 : seg;
    int r = w >> 3, c4 = w & 7;
    const float* g = tile ? (Kf + (krow0 + r) * DD) : (Qf + (qrow0 + r) * DD);
    cp_async16(fbase + (tile ? 16384u : 0u) + (uint32_t)w * 16u, g + kb + c4 * 4);
  }
  cp_commit();
}

__device__ __forceinline__ void qks_convert(uint32_t fbase, uint32_t sbase,
                                            int p, int tid) {
#pragma unroll
  for (int i = 0; i < 6; i++) {
    int seg = tid + i * 512;
    int tile = (seg >= 1024);
    int w = tile ? seg - 1024 : seg;
    uint32_t faddr = fbase + (tile ? 16384u : 0u) + (uint32_t)w * 16u;
    float4 v;
    asm volatile("ld.shared.v4.b32 {%0,%1,%2,%3}, [%4];"
                 : "=f"(v.x), "=f"(v.y), "=f"(v.z), "=f"(v.w) : "r"(faddr));
    __half h0 = __float2half(v.x), h1 = __float2half(v.y);
    __half h2 = __float2half(v.z), h3 = __float2half(v.w);
    int r = w >> 3, c4 = w & 7;
    uint32_t base = tile ? QBW : QAW;
    uint32_t o = (uint32_t)r * 128u + (uint32_t)p * 64u + (uint32_t)c4 * 8u;
    sts8h(base + SWZ(o), h0, h1, h2, h3);
  }
}

// ---------------------------------------------------------------------------
// qks part: h = bid>>1, q0 = (bid&1)*128. Threefry hidden in main loop.
// ---------------------------------------------------------------------------
__device__ void qks_part(int bid, uint32_t sbase, char* smem,
                         const float* __restrict__ Qf, const float* __restrict__ Kf,
                         const float* __restrict__ mask, __half* __restrict__ phi) {
  const int tid = threadIdx.x, wid = tid >> 5, lid = tid & 31;
  const int warp_m = wid >> 2, warp_n = wid & 3;
  const int m0 = warp_m * 32, n0 = warp_n * 64;
  const int q0 = (bid & 1) * 128;
  const int h = bid >> 1;
  const int rr = lid >> 2, cc = lid & 3;

  const size_t qrow0 = (size_t)h * SS + q0;
  const size_t krow0 = (size_t)h * SS;

  float acc[2][8][4];
#pragma unroll
  for (int mi = 0; mi < 2; mi++)
#pragma unroll
    for (int ni = 0; ni < 8; ni++)
#pragma unroll
      for (int j = 0; j < 4; j++) acc[mi][ni][j] = 0.0f;

  uint32_t keepbits[2] = {0u, 0u};

  const int NC = DD / 32;  // 64
  qks_cp(QF(0), Qf, Kf, qrow0, krow0, 0, tid);
  qks_cp(QF(1), Qf, Kf, qrow0, krow0, 32, tid);
  qks_cp(QF(2), Qf, Kf, qrow0, krow0, 64, tid);
  cp_wait2();
  qks_convert(QF(0), sbase, 0, tid);
  __syncthreads();

  for (int ck = 0; ck < NC; ck++) {
    const bool have3 = (ck + 3 < NC);
    if (have3) qks_cp(QF((ck + 3) % 3), Qf, Kf, qrow0, krow0, (ck + 3) * 32, tid);

    // one dropout draw per iteration, hidden under the MMA (ALU pipe idle)
    {
      const int e = ck;                 // 0..63, exactly 64 draws needed
      const int emi = (e >> 5) & 1, ehf = (e >> 4) & 1;
      const int eni = (e >> 1) & 7, ejj = e & 1;
      const int er = q0 + m0 + emi * 16 + ehf * 8 + rr;
      const int ec = n0 + eni * 8 + cc * 2 + ejj;
      const uint32_t idx = ((uint32_t)h * SS + (uint32_t)er) * SS + (uint32_t)ec;
      if (keep_draw(idx)) keepbits[e >> 5] |= (1u << (e & 31));
    }

    {
      const int p = ck & 1;
#pragma unroll
      for (int ks = 0; ks < 2; ks++) {
        uint32_t a[2][4], b[4][4];
#pragma unroll
        for (int mi = 0; mi < 2; mi++)
          ldsm_x4(a_frag_addr(QAW, m0 + mi * 16, ks, p, lid), a[mi]);
#pragma unroll
        for (int nj = 0; nj < 4; nj++)
          ldsm_x4(b_frag_addr(QBW, n0 + nj * 16, ks, p, lid), b[nj]);
#pragma unroll
        for (int mi = 0; mi < 2; mi++)
#pragma unroll
          for (int ni = 0; ni < 8; ni++) {
            uint32_t bb[2] = { b[ni >> 1][(ni & 1) * 2], b[ni >> 1][(ni & 1) * 2 + 1] };
            mma16816(acc[mi][ni], a[mi], bb);
          }
      }
    }
    if (ck + 1 < NC) {
      if (have3) cp_wait2();
      else if (ck + 2 < NC) cp_wait1();
      else cp_wait0();
      qks_convert(QF((ck + 1) % 3), sbase, (ck + 1) & 1, tid);
    }
    __syncthreads();
  }

  // ---- scale + mask ----
  const float scale = 0.022097086912079608f;  // 1/sqrt(2048)
#pragma unroll
  for (int mi = 0; mi < 2; mi++)
#pragma unroll
    for (int ni = 0; ni < 8; ni++)
#pragma unroll
      for (int j = 0; j < 4; j++) {
        const int r = q0 + m0 + mi * 16 + (j >> 1) * 8 + rr;
        const int c = n0 + ni * 8 + cc * 2 + (j & 1);
        acc[mi][ni][j] = acc[mi][ni][j] * scale + mask[(size_t)r * SS + c];
      }

  // ---- row softmax across 4 n-warps ----
  float* sred = (float*)smem;
  float rmax[2][2], rsum[2][2];
#pragma unroll
  for (int mi = 0; mi < 2; mi++)
#pragma unroll
    for (int hf = 0; hf < 2; hf++) {
      float m = -3.4e38f;
#pragma unroll
      for (int ni = 0; ni < 8; ni++) {
        m = fmaxf(m, acc[mi][ni][hf * 2 + 0]);
        m = fmaxf(m, acc[mi][ni][hf * 2 + 1]);
      }
      m = fmaxf(m, __shfl_xor_sync(0xffffffffu, m, 1));
      m = fmaxf(m, __shfl_xor_sync(0xffffffffu, m, 2));
      if (cc == 0) sred[(m0 + mi * 16 + hf * 8 + rr) * 4 + warp_n] = m;
    }
  __syncthreads();
#pragma unroll
  for (int mi = 0; mi < 2; mi++)
#pragma unroll
    for (int hf = 0; hf < 2; hf++) {
      const int row = m0 + mi * 16 + hf * 8 + rr;
      rmax[mi][hf] = fmaxf(fmaxf(sred[row * 4 + 0], sred[row * 4 + 1]),
                           fmaxf(sred[row * 4 + 2], sred[row * 4 + 3]));
    }
  __syncthreads();
#pragma unroll
  for (int mi = 0; mi < 2; mi++)
#pragma unroll
    for (int hf = 0; hf < 2; hf++) {
      float s = 0.0f;
#pragma unroll
      for (int ni = 0; ni < 8; ni++) {
        float e0 = expf(acc[mi][ni][hf * 2 + 0] - rmax[mi][hf]);
        float e1 = expf(acc[mi][ni][hf * 2 + 1] - rmax[mi][hf]);
        acc[mi][ni][hf * 2 + 0] = e0;
        acc[mi][ni][hf * 2 + 1] = e1;
        s += e0 + e1;
      }
      s += __shfl_xor_sync(0xffffffffu, s, 1);
      s += __shfl_xor_sync(0xffffffffu, s, 2);
      if (cc == 0) sred[(m0 + mi * 16 + hf * 8 + rr) * 4 + warp_n] = s;
    }
  __syncthreads();
#pragma unroll
  for (int mi = 0; mi < 2; mi++)
#pragma unroll
    for (int hf = 0; hf < 2; hf++) {
      const int row = m0 + mi * 16 + hf * 8 + rr;
      rsum[mi][hf] = sred[row * 4 + 0] + sred[row * 4 + 1] +
                     sred[row * 4 + 2] + sred[row * 4 + 3];
    }

  // ---- dropout (precomputed bits) + fp16 store ----
#pragma unroll
  for (int mi = 0; mi < 2; mi++)
#pragma unroll
    for (int hf = 0; hf < 2; hf++) {
      const int r = q0 + m0 + mi * 16 + hf * 8 + rr;
      const float inv = 1.0f / rsum[mi][hf];
#pragma unroll
      for (int ni = 0; ni < 8; ni++) {
        const int c = n0 + ni * 8 + cc * 2;
        const int e0 = ((mi * 2 + hf) * 8 + ni) * 2;
        float p0 = acc[mi][ni][hf * 2 + 0] * inv;
        float p1 = acc[mi][ni][hf * 2 + 1] * inv;
        p0 = ((keepbits[e0 >> 5] >> (e0 & 31)) & 1u) ? (p0 / 0.1f) : 0.0f;
        p1 = ((keepbits[(e0 + 1) >> 5] >> ((e0 + 1) & 31)) & 1u) ? (p1 / 0.1f) : 0.0f;
        const size_t o = ((size_t)h * SS + r) * SS + c;
        *(__half2*)(phi + o) = __half2(__float2half(p0), __float2half(p1));
      }
    }

  // ---- publish ----
  __threadfence();
  __syncthreads();
  if (tid == 0) atomicAdd(&g_flag[h], 1);
}

// ---------------------------------------------------------------------------
// pv part: pid = bid-256; h = pid>>4; d0 = (pid&15)*128. Waits g_flag[h]==2.
// V chunks 0..1 prefetched BEFORE the spin (independent of P).
// ---------------------------------------------------------------------------
__device__ __forceinline__ void pv_vcp(uint32_t fv, const float* __restrict__ Vf,
                                       size_t vrow0, int d0, int ck, int tid) {
#pragma unroll
  for (int i = 0; i < 2; i++) {
    int w = tid + i * 512;              // 0..1023 : 32 s x 32 float4
    int s = w >> 5, d4 = w & 31;
    cp_async16(fv + (uint32_t)w * 16u, Vf + (vrow0 + ck * 32 + s) * DD + d0 + d4 * 4);
  }
  cp_commit();
}

__device__ __forceinline__ void pv_vconvert(uint32_t fv, int ckp, uint32_t sbase, int tid) {
#pragma unroll
  for (int i = 0; i < 2; i++) {
    int w = tid + i * 512;
    int s = w >> 5, d4 = w & 31;
    float4 v;
    asm volatile("ld.shared.v4.b32 {%0,%1,%2,%3}, [%4];"
                 : "=f"(v.x), "=f"(v.y), "=f"(v.z), "=f"(v.w)
                 : "r"(fv + (uint32_t)w * 16u));
    int half = d4 >> 4, dl4 = d4 & 15;
    uint32_t off = SWZ(((uint32_t)(ckp * 32 + s)) * 128u + (uint32_t)dl4 * 8u);
    sts8h(VTW + (uint32_t)half * 8192u + off,
          __float2half(v.x), __float2half(v.y),
          __float2half(v.z), __float2half(v.w));
  }
}

__device__ void pv_part(int pid, uint32_t sbase,
                        const __half* __restrict__ Phi,
                        const float* __restrict__ Vf, float* __restrict__ out) {
  const int tid = threadIdx.x, wid = tid >> 5, lid = tid & 31;
  const int warp_m = wid >> 1, nhalf = wid & 1;
  const int m0 = warp_m * 32;
  const int h = pid >> 4;
  const int d0 = (pid & 15) * 128;

  const size_t vrow0 = (size_t)h * SS;

  // V prefetch (does NOT depend on P)
  pv_vcp(VF(0), Vf, vrow0, d0, 0, tid);
  pv_vcp(VF(1), Vf, vrow0, d0, 1, tid);

  // wait for both qks CTAs of this head (acquire loads, no atomic RMW storm)
  if (tid == 0) {
    int v;
    const int* fp = &g_flag[h];
    do {
      asm volatile("ld.global.acquire.gpu.b32 %0, [%1];" : "=r"(v) : "l"(fp));
      if (v < 2) __nanosleep(256);
    } while (v < 2);
  }
  __syncthreads();

  // load P tile resident: 8192 x 16B
#pragma unroll
  for (int i = 0; i < 16; i++) {
    int w = tid + i * 512;              // 0..8191
    int r = w >> 5, c32 = w & 31;
    int kb = c32 >> 3, c16 = c32 & 7;
    cp_async16(PW(kb) + SWZ((uint32_t)r * 128u + (uint32_t)c16 * 16u),
               Phi + ((size_t)h * SS + r) * SS + kb * 64 + c16 * 8);
  }
  cp_commit();
  cp_wait0();                           // P + V0 + V1 all landed
  pv_vconvert(VF(0), 0, sbase, tid);
  __syncthreads();

  float acc[2][8][4];
#pragma unroll
  for (int mi = 0; mi < 2; mi++)
#pragma unroll
    for (int ni = 0; ni < 8; ni++)
#pragma unroll
      for (int j = 0; j < 4; j++) acc[mi][ni][j] = 0.0f;

  const int NC = SS / 32;  // 8
  for (int ck = 0; ck < NC; ck++) {
    const bool have2 = (ck + 2 < NC);
    if (have2) pv_vcp(VF(ck & 1), Vf, vrow0, d0, ck + 2, tid);
    {
      const uint32_t taw = PW(ck >> 1);
      const int p = ck & 1;
#pragma unroll
      for (int ks = 0; ks < 2; ks++) {
        uint32_t a[2][4], b[4][4];
#pragma unroll
        for (int mi = 0; mi < 2; mi++)
          ldsm_x4(a_frag_addr(taw, m0 + mi * 16, ks, p, lid), a[mi]);
#pragma unroll
        for (int nj = 0; nj < 4; nj++)
          ldsm_x4_t(v_frag_addr(VTW, nhalf, nj * 16, ks, p, lid), b[nj]);
#pragma unroll
        for (int mi = 0; mi < 2; mi++)
#pragma unroll
          for (int ni = 0; ni < 8; ni++) {
            uint32_t bb[2] = { b[ni >> 1][(ni & 1) * 2], b[ni >> 1][(ni & 1) * 2 + 1] };
            mma16816(acc[mi][ni], a[mi], bb);
          }
      }
    }
    if (ck + 1 < NC) {
      if (have2) cp_wait1(); else cp_wait0();
      pv_vconvert(VF((ck + 1) & 1), (ck + 1) & 1, sbase, tid);
    }
    __syncthreads();
  }

#pragma unroll
  for (int mi = 0; mi < 2; mi++) {
    const int r0 = m0 + mi * 16 + (lid >> 2);
#pragma unroll
    for (int ni = 0; ni < 8; ni++) {
      const int c = d0 + nhalf * 64 + ni * 8 + (lid & 3) * 2;
#pragma unroll
      for (int half = 0; half < 2; half++) {
        const int r = r0 + half * 8;
        *(float2*)(out + ((size_t)h * SS + r) * DD + c) =
            make_float2(acc[mi][ni][half * 2 + 0], acc[mi][ni][half * 2 + 1]);
      }
    }
  }
}

// ---------------------------------------------------------------------------
// Mega kernel: CTAs [0,256) = qks ; [256, 2304) = pv.
// ---------------------------------------------------------------------------
__global__ __launch_bounds__(512, 1) void attn_mega(
    const float* __restrict__ Qf, const float* __restrict__ Kf,
    const float* __restrict__ Vf, const float* __restrict__ mask,
    __half* __restrict__ phi, float* __restrict__ out) {
  extern __shared__ char smem[];
  const uint32_t sbase = smem_to_u32(smem);
  const int bid = blockIdx.x;
  if (bid < 256) {
    qks_part(bid, sbase, smem, Qf, Kf, mask, phi);
  } else {
    pv_part(bid - 256, sbase, phi, Vf, out);
  }
}

// ---------------------------------------------------------------------------
// Launch
// ---------------------------------------------------------------------------
extern "C" void kernel_launch(void* const* d_in, const int* in_sizes, int n_in,
                              void* d_out, int out_size) {
  const float* Q = (const float*)d_in[0];
  const float* K = (const float*)d_in[1];
  const float* V = (const float*)d_in[2];
  const float* mask = (const float*)d_in[3];
  float* out = (float*)d_out;

  __half* phi; int* flag;
  cudaGetSymbolAddress((void**)&phi, g_phi);
  cudaGetSymbolAddress((void**)&flag, g_flag);

  cudaMemsetAsync(flag, 0, HH * sizeof(int));

  cudaFuncSetAttribute(attn_mega, cudaFuncAttributeMaxDynamicSharedMemorySize,
                       MEGA_SMEM);
  attn_mega<<<2304, 512, MEGA_SMEM>>>(Q, K, V, mask, phi, out);
}

// round 16
// speedup vs baseline: 1.0662x; 1.0662x over previous
#include <cuda_runtime.h>
#include <cuda_fp16.h>
#include <cstdint>

// B=1, H=128, S=256, D=2048, fp32 in/out.
#define HH 128
#define SS 256
#define DD 2048

// ---------------------------------------------------------------------------
// Device scratch (no allocs allowed anywhere).
// ---------------------------------------------------------------------------
__device__ __half g_phi[(size_t)HH * SS * SS];    // P fp16 [h,q,s]
__device__ int    g_flag[HH];                      // per-head completion count

// ---------------------------------------------------------------------------
// Helpers
// ---------------------------------------------------------------------------
__device__ __forceinline__ uint32_t smem_to_u32(const void* p) {
  uint32_t a;
  asm("{ .reg .u64 t; cvta.to.shared.u64 t, %1; cvt.u32.u64 %0, t; }" : "=r"(a) : "l"(p));
  return a;
}
#define SWZ(o) ((o) ^ (((o) >> 3) & 0x70))

__device__ __forceinline__ void cp_async16(uint32_t dst, const void* src) {
  asm volatile("cp.async.cg.shared.global [%0], [%1], 16;" :: "r"(dst), "l"(src) : "memory");
}
__device__ __forceinline__ void cp_commit() {
  asm volatile("cp.async.commit_group;" ::: "memory");
}
__device__ __forceinline__ void cp_wait0() {
  asm volatile("cp.async.wait_group 0;" ::: "memory");
}
__device__ __forceinline__ void cp_wait1() {
  asm volatile("cp.async.wait_group 1;" ::: "memory");
}
__device__ __forceinline__ void cp_wait2() {
  asm volatile("cp.async.wait_group 2;" ::: "memory");
}

__device__ __forceinline__ void ldsm_x4(uint32_t addr, uint32_t* r) {
  asm volatile("ldmatrix.sync.aligned.m8n8.x4.shared.b16 {%0,%1,%2,%3}, [%4];"
               : "=r"(r[0]), "=r"(r[1]), "=r"(r[2]), "=r"(r[3]) : "r"(addr));
}
__device__ __forceinline__ void ldsm_x4_t(uint32_t addr, uint32_t* r) {
  asm volatile("ldmatrix.sync.aligned.m8n8.x4.trans.shared.b16 {%0,%1,%2,%3}, [%4];"
               : "=r"(r[0]), "=r"(r[1]), "=r"(r[2]), "=r"(r[3]) : "r"(addr));
}

__device__ __forceinline__ void mma16816(float* c, const uint32_t* a, const uint32_t* b) {
  asm volatile(
      "mma.sync.aligned.m16n8k16.row.col.f32.f16.f16.f32 "
      "{%0,%1,%2,%3}, {%4,%5,%6,%7}, {%8,%9}, {%0,%1,%2,%3};"
      : "+f"(c[0]), "+f"(c[1]), "+f"(c[2]), "+f"(c[3])
      : "r"(a[0]), "r"(a[1]), "r"(a[2]), "r"(a[3]), "r"(b[0]), "r"(b[1]));
}

__device__ __forceinline__ void sts8h(uint32_t addr, __half a, __half b,
                                      __half c, __half d) {
  __half2 p0(a, b), p1(c, d);
  asm volatile("st.shared.v2.b32 [%0], {%1, %2};" ::
               "r"(addr), "r"(*(uint32_t*)&p0), "r"(*(uint32_t*)&p1) : "memory");
}

// Window tile rows: 128B hold 64 k fp16 = two 32-k chunks; p = chunk parity
// selects the 64B half; ks = 16-k step within chunk. SW128 swizzled.
__device__ __forceinline__ uint32_t a_frag_addr(uint32_t tb, int mt, int ks, int p, int lid) {
  uint32_t off = (uint32_t)(mt + (lid & 15)) * 128 + p * 64 + ks * 32 + ((lid >> 4) * 16);
  return tb + SWZ(off);
}
__device__ __forceinline__ uint32_t b_frag_addr(uint32_t tb, int nt, int ks, int p, int lid) {
  uint32_t off = (uint32_t)(nt + ((lid >> 4) & 1) * 8 + (lid & 7)) * 128
               + p * 64 + ks * 32 + (((lid >> 3) & 1) * 16);
  return tb + SWZ(off);
}
// V trans window: per 64-d half 8KB: 64 s-rows (two chunks) x 128B (64 d fp16).
__device__ __forceinline__ uint32_t v_frag_addr(uint32_t tvw, int half, int nt,
                                                int ks, int ckp, int lid) {
  uint32_t base = tvw + (uint32_t)half * 8192u;
  uint32_t row = (uint32_t)(ckp * 32 + ks * 16 + ((lid >> 3) & 1) * 8 + (lid & 7));
  uint32_t col = (uint32_t)(nt + ((lid >> 4) & 1) * 8) * 2;
  return base + SWZ(row * 128 + col);
}

// ---------------------------------------------------------------------------
// JAX threefry2x32 (20 rounds) — exact; partitionable counter layout.
// ---------------------------------------------------------------------------
__device__ __forceinline__ uint32_t rotl32(uint32_t x, int r) {
  return (x << r) | (x >> (32 - r));
}
__device__ __forceinline__ void threefry2x32(uint32_t k0, uint32_t k1,
                                             uint32_t& x0, uint32_t& x1) {
  const uint32_t ks0 = k0, ks1 = k1, ks2 = k0 ^ k1 ^ 0x1BD11BDAu;
  x0 += ks0; x1 += ks1;
#define TF_R(r) { x0 += x1; x1 = rotl32(x1, r); x1 ^= x0; }
  TF_R(13) TF_R(15) TF_R(26) TF_R(6)
  x0 += ks1; x1 += ks2 + 1u;
  TF_R(17) TF_R(29) TF_R(16) TF_R(24)
  x0 += ks2; x1 += ks0 + 2u;
  TF_R(13) TF_R(15) TF_R(26) TF_R(6)
  x0 += ks0; x1 += ks1 + 3u;
  TF_R(17) TF_R(29) TF_R(16) TF_R(24)
  x0 += ks1; x1 += ks2 + 4u;
  TF_R(13) TF_R(15) TF_R(26) TF_R(6)
  x0 += ks2; x1 += ks0 + 5u;
#undef TF_R
}
__device__ __forceinline__ bool keep_draw(uint32_t i) {
  uint32_t x0 = 0u, x1 = i;
  threefry2x32(0u, 42u, x0, x1);
  const uint32_t bits = x0 ^ x1;
  const float u = __uint_as_float((bits >> 9) | 0x3F800000u) - 1.0f;
  return u < 0.1f;
}

// ===========================================================================
// Shared smem maps (per-CTA, 192KB launch smem).
// qks part: QF(0..2) 3x48KB @0 ; QAW 16KB @147456 ; QBW 32KB @163840.
// pv  part: PW(0..3) P resident 4x32KB @0 ; VF(0..1) 2x16KB @131072 ;
//           VT 16KB @163840.
// ===========================================================================
#define QF(s) (sbase + (uint32_t)(s) * 49152u)
#define QAW   (sbase + 147456u)
#define QBW   (sbase + 163840u)
#define PW(k) (sbase + (uint32_t)(k) * 32768u)
#define VF(s) (sbase + 131072u + (uint32_t)(s) * 16384u)
#define VTW   (sbase + 163840u)
#define MEGA_SMEM 196608

__device__ __forceinline__ void qks_cp(
    uint32_t fbase, const float* __restrict__ Qf, const float* __restrict__ Kf,
    size_t qrow0, size_t krow0, int kb, int tid) {
#pragma unroll
  for (int i = 0; i < 6; i++) {
    int seg = tid + i * 512;            // 0..3071 : 1024 A + 2048 B
    int tile = (seg >= 1024);
    int w = tile ? seg - 1024 : seg;
    int r = w >> 3, c4 = w & 7;
    const float* g = tile ? (Kf + (krow0 + r) * DD) : (Qf + (qrow0 + r) * DD);
    cp_async16(fbase + (tile ? 16384u : 0u) + (uint32_t)w * 16u, g + kb + c4 * 4);
  }
  cp_commit();
}

__device__ __forceinline__ void qks_convert(uint32_t fbase, uint32_t sbase,
                                            int p, int tid) {
#pragma unroll
  for (int i = 0; i < 6; i++) {
    int seg = tid + i * 512;
    int tile = (seg >= 1024);
    int w = tile ? seg - 1024 : seg;
    uint32_t faddr = fbase + (tile ? 16384u : 0u) + (uint32_t)w * 16u;
    float4 v;
    asm volatile("ld.shared.v4.b32 {%0,%1,%2,%3}, [%4];"
                 : "=f"(v.x), "=f"(v.y), "=f"(v.z), "=f"(v.w) : "r"(faddr));
    __half h0 = __float2half(v.x), h1 = __float2half(v.y);
    __half h2 = __float2half(v.z), h3 = __float2half(v.w);
    int r = w >> 3, c4 = w & 7;
    uint32_t base = tile ? QBW : QAW;
    uint32_t o = (uint32_t)r * 128u + (uint32_t)p * 64u + (uint32_t)c4 * 8u;
    sts8h(base + SWZ(o), h0, h1, h2, h3);
  }
}

// ---------------------------------------------------------------------------
// qks part (r12 body): h = bid>>1, q0 = (bid&1)*128. Sets g_flag[h] at end.
// ---------------------------------------------------------------------------
__device__ void qks_part(int bid, uint32_t sbase, char* smem,
                         const float* __restrict__ Qf, const float* __restrict__ Kf,
                         const float* __restrict__ mask, __half* __restrict__ phi) {
  const int tid = threadIdx.x, wid = tid >> 5, lid = tid & 31;
  const int warp_m = wid >> 2, warp_n = wid & 3;
  const int m0 = warp_m * 32, n0 = warp_n * 64;
  const int q0 = (bid & 1) * 128;
  const int h = bid >> 1;

  const size_t qrow0 = (size_t)h * SS + q0;
  const size_t krow0 = (size_t)h * SS;

  float acc[2][8][4];
#pragma unroll
  for (int mi = 0; mi < 2; mi++)
#pragma unroll
    for (int ni = 0; ni < 8; ni++)
#pragma unroll
      for (int j = 0; j < 4; j++) acc[mi][ni][j] = 0.0f;

  const int NC = DD / 32;  // 64
  qks_cp(QF(0), Qf, Kf, qrow0, krow0, 0, tid);
  qks_cp(QF(1), Qf, Kf, qrow0, krow0, 32, tid);
  qks_cp(QF(2), Qf, Kf, qrow0, krow0, 64, tid);
  cp_wait2();
  qks_convert(QF(0), sbase, 0, tid);
  __syncthreads();

  for (int ck = 0; ck < NC; ck++) {
    const bool have3 = (ck + 3 < NC);
    if (have3) qks_cp(QF((ck + 3) % 3), Qf, Kf, qrow0, krow0, (ck + 3) * 32, tid);
    {
      const int p = ck & 1;
#pragma unroll
      for (int ks = 0; ks < 2; ks++) {
        uint32_t a[2][4], b[4][4];
#pragma unroll
        for (int mi = 0; mi < 2; mi++)
          ldsm_x4(a_frag_addr(QAW, m0 + mi * 16, ks, p, lid), a[mi]);
#pragma unroll
        for (int nj = 0; nj < 4; nj++)
          ldsm_x4(b_frag_addr(QBW, n0 + nj * 16, ks, p, lid), b[nj]);
#pragma unroll
        for (int mi = 0; mi < 2; mi++)
#pragma unroll
          for (int ni = 0; ni < 8; ni++) {
            uint32_t bb[2] = { b[ni >> 1][(ni & 1) * 2], b[ni >> 1][(ni & 1) * 2 + 1] };
            mma16816(acc[mi][ni], a[mi], bb);
          }
      }
    }
    if (ck + 1 < NC) {
      if (have3) cp_wait2();
      else if (ck + 2 < NC) cp_wait1();
      else cp_wait0();
      qks_convert(QF((ck + 1) % 3), sbase, (ck + 1) & 1, tid);
    }
    __syncthreads();
  }

  // ---- scale + mask ----
  const float scale = 0.022097086912079608f;  // 1/sqrt(2048)
  const int rr = lid >> 2, cc = lid & 3;
#pragma unroll
  for (int mi = 0; mi < 2; mi++)
#pragma unroll
    for (int ni = 0; ni < 8; ni++)
#pragma unroll
      for (int j = 0; j < 4; j++) {
        const int r = q0 + m0 + mi * 16 + (j >> 1) * 8 + rr;
        const int c = n0 + ni * 8 + cc * 2 + (j & 1);
        acc[mi][ni][j] = acc[mi][ni][j] * scale + mask[(size_t)r * SS + c];
      }

  // ---- row softmax across 4 n-warps ----
  float* sred = (float*)smem;
  float rmax[2][2], rsum[2][2];
#pragma unroll
  for (int mi = 0; mi < 2; mi++)
#pragma unroll
    for (int hf = 0; hf < 2; hf++) {
      float m = -3.4e38f;
#pragma unroll
      for (int ni = 0; ni < 8; ni++) {
        m = fmaxf(m, acc[mi][ni][hf * 2 + 0]);
        m = fmaxf(m, acc[mi][ni][hf * 2 + 1]);
      }
      m = fmaxf(m, __shfl_xor_sync(0xffffffffu, m, 1));
      m = fmaxf(m, __shfl_xor_sync(0xffffffffu, m, 2));
      if (cc == 0) sred[(m0 + mi * 16 + hf * 8 + rr) * 4 + warp_n] = m;
    }
  __syncthreads();
#pragma unroll
  for (int mi = 0; mi < 2; mi++)
#pragma unroll
    for (int hf = 0; hf < 2; hf++) {
      const int row = m0 + mi * 16 + hf * 8 + rr;
      rmax[mi][hf] = fmaxf(fmaxf(sred[row * 4 + 0], sred[row * 4 + 1]),
                           fmaxf(sred[row * 4 + 2], sred[row * 4 + 3]));
    }
  __syncthreads();
#pragma unroll
  for (int mi = 0; mi < 2; mi++)
#pragma unroll
    for (int hf = 0; hf < 2; hf++) {
      float s = 0.0f;
#pragma unroll
      for (int ni = 0; ni < 8; ni++) {
        float e0 = expf(acc[mi][ni][hf * 2 + 0] - rmax[mi][hf]);
        float e1 = expf(acc[mi][ni][hf * 2 + 1] - rmax[mi][hf]);
        acc[mi][ni][hf * 2 + 0] = e0;
        acc[mi][ni][hf * 2 + 1] = e1;
        s += e0 + e1;
      }
      s += __shfl_xor_sync(0xffffffffu, s, 1);
      s += __shfl_xor_sync(0xffffffffu, s, 2);
      if (cc == 0) sred[(m0 + mi * 16 + hf * 8 + rr) * 4 + warp_n] = s;
    }
  __syncthreads();
#pragma unroll
  for (int mi = 0; mi < 2; mi++)
#pragma unroll
    for (int hf = 0; hf < 2; hf++) {
      const int row = m0 + mi * 16 + hf * 8 + rr;
      rsum[mi][hf] = sred[row * 4 + 0] + sred[row * 4 + 1] +
                     sred[row * 4 + 2] + sred[row * 4 + 3];
    }

  // ---- dropout + fp16 store ----
#pragma unroll
  for (int mi = 0; mi < 2; mi++)
#pragma unroll
    for (int hf = 0; hf < 2; hf++) {
      const int r = q0 + m0 + mi * 16 + hf * 8 + rr;
      const float inv = 1.0f / rsum[mi][hf];
      const uint32_t ibase = ((uint32_t)h * SS + (uint32_t)r) * SS;
#pragma unroll
      for (int ni = 0; ni < 8; ni++) {
        const int c = n0 + ni * 8 + cc * 2;
        float p0 = acc[mi][ni][hf * 2 + 0] * inv;
        float p1 = acc[mi][ni][hf * 2 + 1] * inv;
        p0 = keep_draw(ibase + c)     ? (p0 / 0.1f) : 0.0f;
        p1 = keep_draw(ibase + c + 1) ? (p1 / 0.1f) : 0.0f;
        const size_t o = ((size_t)h * SS + r) * SS + c;
        *(__half2*)(phi + o) = __half2(__float2half(p0), __float2half(p1));
      }
    }

  // ---- publish ----
  __threadfence();
  __syncthreads();
  if (tid == 0) atomicAdd(&g_flag[h], 1);
}

// ---------------------------------------------------------------------------
// pv part: pid = bid-256; h = pid>>4; d0 = (pid&15)*128. Waits g_flag[h]==2.
// Tile 256q x 128d, 16 warps (8m x 2n), warp 32x64. P resident in smem.
// ---------------------------------------------------------------------------
__device__ __forceinline__ void pv_vcp(uint32_t fv, const float* __restrict__ Vf,
                                       size_t vrow0, int d0, int ck, int tid) {
#pragma unroll
  for (int i = 0; i < 2; i++) {
    int w = tid + i * 512;              // 0..1023 : 32 s x 32 float4
    int s = w >> 5, d4 = w & 31;
    cp_async16(fv + (uint32_t)w * 16u, Vf + (vrow0 + ck * 32 + s) * DD + d0 + d4 * 4);
  }
  cp_commit();
}

__device__ __forceinline__ void pv_vconvert(uint32_t fv, int ckp, uint32_t sbase, int tid) {
#pragma unroll
  for (int i = 0; i < 2; i++) {
    int w = tid + i * 512;
    int s = w >> 5, d4 = w & 31;
    float4 v;
    asm volatile("ld.shared.v4.b32 {%0,%1,%2,%3}, [%4];"
                 : "=f"(v.x), "=f"(v.y), "=f"(v.z), "=f"(v.w)
                 : "r"(fv + (uint32_t)w * 16u));
    int half = d4 >> 4, dl4 = d4 & 15;
    uint32_t off = SWZ(((uint32_t)(ckp * 32 + s)) * 128u + (uint32_t)dl4 * 8u);
    sts8h(VTW + (uint32_t)half * 8192u + off,
          __float2half(v.x), __float2half(v.y),
          __float2half(v.z), __float2half(v.w));
  }
}

__device__ void pv_part(int pid, uint32_t sbase,
                        const __half* __restrict__ Phi,
                        const float* __restrict__ Vf, float* __restrict__ out) {
  const int tid = threadIdx.x, wid = tid >> 5, lid = tid & 31;
  const int warp_m = wid >> 1, nhalf = wid & 1;
  const int m0 = warp_m * 32;
  const int h = pid >> 4;
  const int d0 = (pid & 15) * 128;

  const size_t vrow0 = (size_t)h * SS;

  // wait for both qks CTAs of this head — acquire-load poll (no atomic storm)
  if (tid == 0) {
    int v;
    const int* fp = &g_flag[h];
    do {
      asm volatile("ld.global.acquire.gpu.b32 %0, [%1];" : "=r"(v) : "l"(fp));
      if (v < 2) __nanosleep(256);
    } while (v < 2);
  }
  __syncthreads();

  // load P tile resident: 8192 x 16B (cp.async.cg -> L2, coherent with flag)
#pragma unroll
  for (int i = 0; i < 16; i++) {
    int w = tid + i * 512;              // 0..8191
    int r = w >> 5, c32 = w & 31;
    int kb = c32 >> 3, c16 = c32 & 7;
    cp_async16(PW(kb) + SWZ((uint32_t)r * 128u + (uint32_t)c16 * 16u),
               Phi + ((size_t)h * SS + r) * SS + kb * 64 + c16 * 8);
  }
  cp_commit();
  pv_vcp(VF(0), Vf, vrow0, d0, 0, tid);
  pv_vcp(VF(1), Vf, vrow0, d0, 1, tid);
  cp_wait1();                           // P + V0 done
  pv_vconvert(VF(0), 0, sbase, tid);
  __syncthreads();

  float acc[2][8][4];
#pragma unroll
  for (int mi = 0; mi < 2; mi++)
#pragma unroll
    for (int ni = 0; ni < 8; ni++)
#pragma unroll
      for (int j = 0; j < 4; j++) acc[mi][ni][j] = 0.0f;

  const int NC = SS / 32;  // 8
  for (int ck = 0; ck < NC; ck++) {
    const bool have2 = (ck + 2 < NC);
    if (have2) pv_vcp(VF(ck & 1), Vf, vrow0, d0, ck + 2, tid);
    {
      const uint32_t taw = PW(ck >> 1);
      const int p = ck & 1;
#pragma unroll
      for (int ks = 0; ks < 2; ks++) {
        uint32_t a[2][4], b[4][4];
#pragma unroll
        for (int mi = 0; mi < 2; mi++)
          ldsm_x4(a_frag_addr(taw, m0 + mi * 16, ks, p, lid), a[mi]);
#pragma unroll
        for (int nj = 0; nj < 4; nj++)
          ldsm_x4_t(v_frag_addr(VTW, nhalf, nj * 16, ks, p, lid), b[nj]);
#pragma unroll
        for (int mi = 0; mi < 2; mi++)
#pragma unroll
          for (int ni = 0; ni < 8; ni++) {
            uint32_t bb[2] = { b[ni >> 1][(ni & 1) * 2], b[ni >> 1][(ni & 1) * 2 + 1] };
            mma16816(acc[mi][ni], a[mi], bb);
          }
      }
    }
    if (ck + 1 < NC) {
      if (have2) cp_wait1(); else cp_wait0();
      pv_vconvert(VF((ck + 1) & 1), (ck + 1) & 1, sbase, tid);
    }
    __syncthreads();
  }

#pragma unroll
  for (int mi = 0; mi < 2; mi++) {
    const int r0 = m0 + mi * 16 + (lid >> 2);
#pragma unroll
    for (int ni = 0; ni < 8; ni++) {
      const int c = d0 + nhalf * 64 + ni * 8 + (lid & 3) * 2;
#pragma unroll
      for (int half = 0; half < 2; half++) {
        const int r = r0 + half * 8;
        *(float2*)(out + ((size_t)h * SS + r) * DD + c) =
            make_float2(acc[mi][ni][half * 2 + 0], acc[mi][ni][half * 2 + 1]);
      }
    }
  }
}

// ---------------------------------------------------------------------------
// Mega kernel: CTAs [0,256) = qks ; [256, 2304) = pv.
// ---------------------------------------------------------------------------
__global__ __launch_bounds__(512, 1) void attn_mega(
    const float* __restrict__ Qf, const float* __restrict__ Kf,
    const float* __restrict__ Vf, const float* __restrict__ mask,
    __half* __restrict__ phi, float* __restrict__ out) {
  extern __shared__ char smem[];
  const uint32_t sbase = smem_to_u32(smem);
  const int bid = blockIdx.x;
  if (bid < 256) {
    qks_part(bid, sbase, smem, Qf, Kf, mask, phi);
  } else {
    pv_part(bid - 256, sbase, phi, Vf, out);
  }
}

// ---------------------------------------------------------------------------
// Launch
// ---------------------------------------------------------------------------
extern "C" void kernel_launch(void* const* d_in, const int* in_sizes, int n_in,
                              void* d_out, int out_size) {
  const float* Q = (const float*)d_in[0];
  const float* K = (const float*)d_in[1];
  const float* V = (const float*)d_in[2];
  const float* mask = (const float*)d_in[3];
  float* out = (float*)d_out;

  __half* phi; int* flag;
  cudaGetSymbolAddress((void**)&phi, g_phi);
  cudaGetSymbolAddress((void**)&flag, g_flag);

  cudaMemsetAsync(flag, 0, HH * sizeof(int));

  cudaFuncSetAttribute(attn_mega, cudaFuncAttributeMaxDynamicSharedMemorySize,
                       MEGA_SMEM);
  attn_mega<<<2304, 512, MEGA_SMEM>>>(Q, K, V, mask, phi, out);
}

// round 17
// speedup vs baseline: 1.0695x; 1.0031x over previous
#include <cuda_runtime.h>
#include <cuda_fp16.h>
#include <cstdint>

// B=1, H=128, S=256, D=2048, fp32 in/out.
#define HH 128
#define SS 256
#define DD 2048

// ---------------------------------------------------------------------------
// Device scratch (no allocs allowed anywhere).
// ---------------------------------------------------------------------------
__device__ __half g_phi[(size_t)HH * SS * SS];    // P fp16 [h,q,s]
__device__ int    g_flag[HH];                      // per-head completion count

// ---------------------------------------------------------------------------
// Helpers
// ---------------------------------------------------------------------------
__device__ __forceinline__ uint32_t smem_to_u32(const void* p) {
  uint32_t a;
  asm("{ .reg .u64 t; cvta.to.shared.u64 t, %1; cvt.u32.u64 %0, t; }" : "=r"(a) : "l"(p));
  return a;
}
#define SWZ(o) ((o) ^ (((o) >> 3) & 0x70))

__device__ __forceinline__ void cp_async16(uint32_t dst, const void* src) {
  asm volatile("cp.async.cg.shared.global [%0], [%1], 16;" :: "r"(dst), "l"(src) : "memory");
}
__device__ __forceinline__ void cp_commit() {
  asm volatile("cp.async.commit_group;" ::: "memory");
}
__device__ __forceinline__ void cp_wait0() {
  asm volatile("cp.async.wait_group 0;" ::: "memory");
}
__device__ __forceinline__ void cp_wait1() {
  asm volatile("cp.async.wait_group 1;" ::: "memory");
}

__device__ __forceinline__ void ldsm_x4(uint32_t addr, uint32_t* r) {
  asm volatile("ldmatrix.sync.aligned.m8n8.x4.shared.b16 {%0,%1,%2,%3}, [%4];"
               : "=r"(r[0]), "=r"(r[1]), "=r"(r[2]), "=r"(r[3]) : "r"(addr));
}
__device__ __forceinline__ void ldsm_x4_t(uint32_t addr, uint32_t* r) {
  asm volatile("ldmatrix.sync.aligned.m8n8.x4.trans.shared.b16 {%0,%1,%2,%3}, [%4];"
               : "=r"(r[0]), "=r"(r[1]), "=r"(r[2]), "=r"(r[3]) : "r"(addr));
}

__device__ __forceinline__ void mma16816(float* c, const uint32_t* a, const uint32_t* b) {
  asm volatile(
      "mma.sync.aligned.m16n8k16.row.col.f32.f16.f16.f32 "
      "{%0,%1,%2,%3}, {%4,%5,%6,%7}, {%8,%9}, {%0,%1,%2,%3};"
      : "+f"(c[0]), "+f"(c[1]), "+f"(c[2]), "+f"(c[3])
      : "r"(a[0]), "r"(a[1]), "r"(a[2]), "r"(a[3]), "r"(b[0]), "r"(b[1]));
}

__device__ __forceinline__ void sts8h(uint32_t addr, __half a, __half b,
                                      __half c, __half d) {
  __half2 p0(a, b), p1(c, d);
  asm volatile("st.shared.v2.b32 [%0], {%1, %2};" ::
               "r"(addr), "r"(*(uint32_t*)&p0), "r"(*(uint32_t*)&p1) : "memory");
}

// Window tile rows: 128B hold 64 k fp16 = two 32-k chunks; p = chunk parity
// selects the 64B half; ks = 16-k step within chunk. SW128 swizzled.
__device__ __forceinline__ uint32_t a_frag_addr(uint32_t tb, int mt, int ks, int p, int lid) {
  uint32_t off = (uint32_t)(mt + (lid & 15)) * 128 + p * 64 + ks * 32 + ((lid >> 4) * 16);
  return tb + SWZ(off);
}
__device__ __forceinline__ uint32_t b_frag_addr(uint32_t tb, int nt, int ks, int p, int lid) {
  uint32_t off = (uint32_t)(nt + ((lid >> 4) & 1) * 8 + (lid & 7)) * 128
               + p * 64 + ks * 32 + (((lid >> 3) & 1) * 16);
  return tb + SWZ(off);
}
// V trans window: per 64-d half 8KB: 64 s-rows (two chunks) x 128B (64 d fp16).
__device__ __forceinline__ uint32_t v_frag_addr(uint32_t tvw, int half, int nt,
                                                int ks, int ckp, int lid) {
  uint32_t base = tvw + (uint32_t)half * 8192u;
  uint32_t row = (uint32_t)(ckp * 32 + ks * 16 + ((lid >> 3) & 1) * 8 + (lid & 7));
  uint32_t col = (uint32_t)(nt + ((lid >> 4) & 1) * 8) * 2;
  return base + SWZ(row * 128 + col);
}

// ---------------------------------------------------------------------------
// JAX threefry2x32 (20 rounds) — exact; partitionable counter layout.
// ---------------------------------------------------------------------------
__device__ __forceinline__ uint32_t rotl32(uint32_t x, int r) {
  return (x << r) | (x >> (32 - r));
}
__device__ __forceinline__ void threefry2x32(uint32_t k0, uint32_t k1,
                                             uint32_t& x0, uint32_t& x1) {
  const uint32_t ks0 = k0, ks1 = k1, ks2 = k0 ^ k1 ^ 0x1BD11BDAu;
  x0 += ks0; x1 += ks1;
#define TF_R(r) { x0 += x1; x1 = rotl32(x1, r); x1 ^= x0; }
  TF_R(13) TF_R(15) TF_R(26) TF_R(6)
  x0 += ks1; x1 += ks2 + 1u;
  TF_R(17) TF_R(29) TF_R(16) TF_R(24)
  x0 += ks2; x1 += ks0 + 2u;
  TF_R(13) TF_R(15) TF_R(26) TF_R(6)
  x0 += ks0; x1 += ks1 + 3u;
  TF_R(17) TF_R(29) TF_R(16) TF_R(24)
  x0 += ks1; x1 += ks2 + 4u;
  TF_R(13) TF_R(15) TF_R(26) TF_R(6)
  x0 += ks2; x1 += ks0 + 5u;
#undef TF_R
}
__device__ __forceinline__ bool keep_draw(uint32_t i) {
  uint32_t x0 = 0u, x1 = i;
  threefry2x32(0u, 42u, x0, x1);
  const uint32_t bits = x0 ^ x1;
  const float u = __uint_as_float((bits >> 9) | 0x3F800000u) - 1.0f;
  return u < 0.1f;
}

// ===========================================================================
// Shared smem maps (per-CTA, 192KB launch smem).
// qks part: QF(0..1) 2x48KB @0 ; WA(0..1) 2x16KB @98304 ; WB(0..1) 2x32KB @131072.
// pv  part: PW(0..3) P resident 4x32KB @0 ; VF(0..1) 2x16KB @131072 ;
//           VT 16KB @163840.
// ===========================================================================
#define QF(s) (sbase + (uint32_t)(s) * 49152u)
#define WA(w) (sbase + 98304u + (uint32_t)(w) * 16384u)
#define WB(w) (sbase + 131072u + (uint32_t)(w) * 32768u)
#define PW(k) (sbase + (uint32_t)(k) * 32768u)
#define VF(s) (sbase + 131072u + (uint32_t)(s) * 16384u)
#define VTW   (sbase + 163840u)
#define MEGA_SMEM 196608

__device__ __forceinline__ void qks_cp(
    uint32_t fbase, const float* __restrict__ Qf, const float* __restrict__ Kf,
    size_t qrow0, size_t krow0, int kb, int tid) {
#pragma unroll
  for (int i = 0; i < 6; i++) {
    int seg = tid + i * 512;            // 0..3071 : 1024 A + 2048 B
    int tile = (seg >= 1024);
    int w = tile ? seg - 1024 : seg;
    int r = w >> 3, c4 = w & 7;
    const float* g = tile ? (Kf + (krow0 + r) * DD) : (Qf + (qrow0 + r) * DD);
    cp_async16(fbase + (tile ? 16384u : 0u) + (uint32_t)w * 16u, g + kb + c4 * 4);
  }
  cp_commit();
}

// Convert one 32-k chunk from fp32 stage into window pair (wa, wb) parity p.
__device__ __forceinline__ void qks_convert(uint32_t fbase, uint32_t wa, uint32_t wb,
                                            int p, int tid) {
#pragma unroll
  for (int i = 0; i < 6; i++) {
    int seg = tid + i * 512;
    int tile = (seg >= 1024);
    int w = tile ? seg - 1024 : seg;
    uint32_t faddr = fbase + (tile ? 16384u : 0u) + (uint32_t)w * 16u;
    float4 v;
    asm volatile("ld.shared.v4.b32 {%0,%1,%2,%3}, [%4];"
                 : "=f"(v.x), "=f"(v.y), "=f"(v.z), "=f"(v.w) : "r"(faddr));
    __half h0 = __float2half(v.x), h1 = __float2half(v.y);
    __half h2 = __float2half(v.z), h3 = __float2half(v.w);
    int r = w >> 3, c4 = w & 7;
    uint32_t base = tile ? wb : wa;
    uint32_t o = (uint32_t)r * 128u + (uint32_t)p * 64u + (uint32_t)c4 * 8u;
    sts8h(base + SWZ(o), h0, h1, h2, h3);
  }
}

// ---------------------------------------------------------------------------
// qks part: h = bid>>1, q0 = (bid&1)*128. 32 double-chunk steps.
// ---------------------------------------------------------------------------
__device__ void qks_part(int bid, uint32_t sbase, char* smem,
                         const float* __restrict__ Qf, const float* __restrict__ Kf,
                         const float* __restrict__ mask, __half* __restrict__ phi) {
  const int tid = threadIdx.x, wid = tid >> 5, lid = tid & 31;
  const int warp_m = wid >> 2, warp_n = wid & 3;
  const int m0 = warp_m * 32, n0 = warp_n * 64;
  const int q0 = (bid & 1) * 128;
  const int h = bid >> 1;

  const size_t qrow0 = (size_t)h * SS + q0;
  const size_t krow0 = (size_t)h * SS;

  float acc[2][8][4];
#pragma unroll
  for (int mi = 0; mi < 2; mi++)
#pragma unroll
    for (int ni = 0; ni < 8; ni++)
#pragma unroll
      for (int j = 0; j < 4; j++) acc[mi][ni][j] = 0.0f;

  const int NSTEP = DD / 64;  // 32 steps, 2 chunks each
  // prologue: chunks 0,1 -> window 0 ; chunks 2,3 in flight
  qks_cp(QF(0), Qf, Kf, qrow0, krow0, 0, tid);
  qks_cp(QF(1), Qf, Kf, qrow0, krow0, 32, tid);
  cp_wait0();
  qks_convert(QF(0), WA(0), WB(0), 0, tid);
  qks_convert(QF(1), WA(0), WB(0), 1, tid);
  qks_cp(QF(0), Qf, Kf, qrow0, krow0, 64, tid);
  qks_cp(QF(1), Qf, Kf, qrow0, krow0, 96, tid);
  __syncthreads();

  for (int t = 0; t < NSTEP; t++) {
    const uint32_t wa = WA(t & 1), wb = WB(t & 1);
#pragma unroll
    for (int p = 0; p < 2; p++) {
#pragma unroll
      for (int ks = 0; ks < 2; ks++) {
        uint32_t a[2][4], b[4][4];
#pragma unroll
        for (int mi = 0; mi < 2; mi++)
          ldsm_x4(a_frag_addr(wa, m0 + mi * 16, ks, p, lid), a[mi]);
#pragma unroll
        for (int nj = 0; nj < 4; nj++)
          ldsm_x4(b_frag_addr(wb, n0 + nj * 16, ks, p, lid), b[nj]);
#pragma unroll
        for (int mi = 0; mi < 2; mi++)
#pragma unroll
          for (int ni = 0; ni < 8; ni++) {
            uint32_t bb[2] = { b[ni >> 1][(ni & 1) * 2], b[ni >> 1][(ni & 1) * 2 + 1] };
            mma16816(acc[mi][ni], a[mi], bb);
          }
      }
    }
    if (t + 1 < NSTEP) {
      cp_wait0();
      qks_convert(QF(0), WA((t + 1) & 1), WB((t + 1) & 1), 0, tid);
      qks_convert(QF(1), WA((t + 1) & 1), WB((t + 1) & 1), 1, tid);
      if (t + 2 < NSTEP) {
        qks_cp(QF(0), Qf, Kf, qrow0, krow0, (2 * t + 4) * 32, tid);
        qks_cp(QF(1), Qf, Kf, qrow0, krow0, (2 * t + 5) * 32, tid);
      }
    }
    __syncthreads();
  }

  // ---- scale + mask ----
  const float scale = 0.022097086912079608f;  // 1/sqrt(2048)
  const int rr = lid >> 2, cc = lid & 3;
#pragma unroll
  for (int mi = 0; mi < 2; mi++)
#pragma unroll
    for (int ni = 0; ni < 8; ni++)
#pragma unroll
      for (int j = 0; j < 4; j++) {
        const int r = q0 + m0 + mi * 16 + (j >> 1) * 8 + rr;
        const int c = n0 + ni * 8 + cc * 2 + (j & 1);
        acc[mi][ni][j] = acc[mi][ni][j] * scale + mask[(size_t)r * SS + c];
      }

  // ---- row softmax across 4 n-warps ----
  float* sred = (float*)smem;
  float rmax[2][2], rsum[2][2];
#pragma unroll
  for (int mi = 0; mi < 2; mi++)
#pragma unroll
    for (int hf = 0; hf < 2; hf++) {
      float m = -3.4e38f;
#pragma unroll
      for (int ni = 0; ni < 8; ni++) {
        m = fmaxf(m, acc[mi][ni][hf * 2 + 0]);
        m = fmaxf(m, acc[mi][ni][hf * 2 + 1]);
      }
      m = fmaxf(m, __shfl_xor_sync(0xffffffffu, m, 1));
      m = fmaxf(m, __shfl_xor_sync(0xffffffffu, m, 2));
      if (cc == 0) sred[(m0 + mi * 16 + hf * 8 + rr) * 4 + warp_n] = m;
    }
  __syncthreads();
#pragma unroll
  for (int mi = 0; mi < 2; mi++)
#pragma unroll
    for (int hf = 0; hf < 2; hf++) {
      const int row = m0 + mi * 16 + hf * 8 + rr;
      rmax[mi][hf] = fmaxf(fmaxf(sred[row * 4 + 0], sred[row * 4 + 1]),
                           fmaxf(sred[row * 4 + 2], sred[row * 4 + 3]));
    }
  __syncthreads();
#pragma unroll
  for (int mi = 0; mi < 2; mi++)
#pragma unroll
    for (int hf = 0; hf < 2; hf++) {
      float s = 0.0f;
#pragma unroll
      for (int ni = 0; ni < 8; ni++) {
        float e0 = expf(acc[mi][ni][hf * 2 + 0] - rmax[mi][hf]);
        float e1 = expf(acc[mi][ni][hf * 2 + 1] - rmax[mi][hf]);
        acc[mi][ni][hf * 2 + 0] = e0;
        acc[mi][ni][hf * 2 + 1] = e1;
        s += e0 + e1;
      }
      s += __shfl_xor_sync(0xffffffffu, s, 1);
      s += __shfl_xor_sync(0xffffffffu, s, 2);
      if (cc == 0) sred[(m0 + mi * 16 + hf * 8 + rr) * 4 + warp_n] = s;
    }
  __syncthreads();
#pragma unroll
  for (int mi = 0; mi < 2; mi++)
#pragma unroll
    for (int hf = 0; hf < 2; hf++) {
      const int row = m0 + mi * 16 + hf * 8 + rr;
      rsum[mi][hf] = sred[row * 4 + 0] + sred[row * 4 + 1] +
                     sred[row * 4 + 2] + sred[row * 4 + 3];
    }

  // ---- dropout + fp16 store ----
#pragma unroll
  for (int mi = 0; mi < 2; mi++)
#pragma unroll
    for (int hf = 0; hf < 2; hf++) {
      const int r = q0 + m0 + mi * 16 + hf * 8 + rr;
      const float inv = 1.0f / rsum[mi][hf];
      const uint32_t ibase = ((uint32_t)h * SS + (uint32_t)r) * SS;
#pragma unroll
      for (int ni = 0; ni < 8; ni++) {
        const int c = n0 + ni * 8 + cc * 2;
        float p0 = acc[mi][ni][hf * 2 + 0] * inv;
        float p1 = acc[mi][ni][hf * 2 + 1] * inv;
        p0 = keep_draw(ibase + c)     ? (p0 / 0.1f) : 0.0f;
        p1 = keep_draw(ibase + c + 1) ? (p1 / 0.1f) : 0.0f;
        const size_t o = ((size_t)h * SS + r) * SS + c;
        *(__half2*)(phi + o) = __half2(__float2half(p0), __float2half(p1));
      }
    }

  // ---- publish ----
  __threadfence();
  __syncthreads();
  if (tid == 0) atomicAdd(&g_flag[h], 1);
}

// ---------------------------------------------------------------------------
// pv part: pid = bid-256; h = pid>>4; d0 = (pid&15)*128. Waits g_flag[h]==2.
// Tile 256q x 128d, 16 warps (8m x 2n), warp 32x64. P resident in smem.
// ---------------------------------------------------------------------------
__device__ __forceinline__ void pv_vcp(uint32_t fv, const float* __restrict__ Vf,
                                       size_t vrow0, int d0, int ck, int tid) {
#pragma unroll
  for (int i = 0; i < 2; i++) {
    int w = tid + i * 512;              // 0..1023 : 32 s x 32 float4
    int s = w >> 5, d4 = w & 31;
    cp_async16(fv + (uint32_t)w * 16u, Vf + (vrow0 + ck * 32 + s) * DD + d0 + d4 * 4);
  }
  cp_commit();
}

__device__ __forceinline__ void pv_vconvert(uint32_t fv, int ckp, uint32_t sbase, int tid) {
#pragma unroll
  for (int i = 0; i < 2; i++) {
    int w = tid + i * 512;
    int s = w >> 5, d4 = w & 31;
    float4 v;
    asm volatile("ld.shared.v4.b32 {%0,%1,%2,%3}, [%4];"
                 : "=f"(v.x), "=f"(v.y), "=f"(v.z), "=f"(v.w)
                 : "r"(fv + (uint32_t)w * 16u));
    int half = d4 >> 4, dl4 = d4 & 15;
    uint32_t off = SWZ(((uint32_t)(ckp * 32 + s)) * 128u + (uint32_t)dl4 * 8u);
    sts8h(VTW + (uint32_t)half * 8192u + off,
          __float2half(v.x), __float2half(v.y),
          __float2half(v.z), __float2half(v.w));
  }
}

__device__ void pv_part(int pid, uint32_t sbase,
                        const __half* __restrict__ Phi,
                        const float* __restrict__ Vf, float* __restrict__ out) {
  const int tid = threadIdx.x, wid = tid >> 5, lid = tid & 31;
  const int warp_m = wid >> 1, nhalf = wid & 1;
  const int m0 = warp_m * 32;
  const int h = pid >> 4;
  const int d0 = (pid & 15) * 128;

  const size_t vrow0 = (size_t)h * SS;

  // wait for both qks CTAs of this head — acquire-load poll
  if (tid == 0) {
    int v;
    const int* fp = &g_flag[h];
    do {
      asm volatile("ld.global.acquire.gpu.b32 %0, [%1];" : "=r"(v) : "l"(fp));
      if (v < 2) __nanosleep(256);
    } while (v < 2);
  }
  __syncthreads();

  // load P tile resident: 8192 x 16B (cp.async.cg -> L2, coherent with flag)
#pragma unroll
  for (int i = 0; i < 16; i++) {
    int w = tid + i * 512;              // 0..8191
    int r = w >> 5, c32 = w & 31;
    int kb = c32 >> 3, c16 = c32 & 7;
    cp_async16(PW(kb) + SWZ((uint32_t)r * 128u + (uint32_t)c16 * 16u),
               Phi + ((size_t)h * SS + r) * SS + kb * 64 + c16 * 8);
  }
  cp_commit();
  pv_vcp(VF(0), Vf, vrow0, d0, 0, tid);
  pv_vcp(VF(1), Vf, vrow0, d0, 1, tid);
  cp_wait1();                           // P + V0 done
  pv_vconvert(VF(0), 0, sbase, tid);
  __syncthreads();

  float acc[2][8][4];
#pragma unroll
  for (int mi = 0; mi < 2; mi++)
#pragma unroll
    for (int ni = 0; ni < 8; ni++)
#pragma unroll
      for (int j = 0; j < 4; j++) acc[mi][ni][j] = 0.0f;

  const int NC = SS / 32;  // 8
  for (int ck = 0; ck < NC; ck++) {
    const bool have2 = (ck + 2 < NC);
    if (have2) pv_vcp(VF(ck & 1), Vf, vrow0, d0, ck + 2, tid);
    {
      const uint32_t taw = PW(ck >> 1);
      const int p = ck & 1;
#pragma unroll
      for (int ks = 0; ks < 2; ks++) {
        uint32_t a[2][4], b[4][4];
#pragma unroll
        for (int mi = 0; mi < 2; mi++)
          ldsm_x4(a_frag_addr(taw, m0 + mi * 16, ks, p, lid), a[mi]);
#pragma unroll
        for (int nj = 0; nj < 4; nj++)
          ldsm_x4_t(v_frag_addr(VTW, nhalf, nj * 16, ks, p, lid), b[nj]);
#pragma unroll
        for (int mi = 0; mi < 2; mi++)
#pragma unroll
          for (int ni = 0; ni < 8; ni++) {
            uint32_t bb[2] = { b[ni >> 1][(ni & 1) * 2], b[ni >> 1][(ni & 1) * 2 + 1] };
            mma16816(acc[mi][ni], a[mi], bb);
          }
      }
    }
    if (ck + 1 < NC) {
      if (have2) cp_wait1(); else cp_wait0();
      pv_vconvert(VF((ck + 1) & 1), (ck + 1) & 1, sbase, tid);
    }
    __syncthreads();
  }

#pragma unroll
  for (int mi = 0; mi < 2; mi++) {
    const int r0 = m0 + mi * 16 + (lid >> 2);
#pragma unroll
    for (int ni = 0; ni < 8; ni++) {
      const int c = d0 + nhalf * 64 + ni * 8 + (lid & 3) * 2;
#pragma unroll
      for (int half = 0; half < 2; half++) {
        const int r = r0 + half * 8;
        *(float2*)(out + ((size_t)h * SS + r) * DD + c) =
            make_float2(acc[mi][ni][half * 2 + 0], acc[mi][ni][half * 2 + 1]);
      }
    }
  }
}

// ---------------------------------------------------------------------------
// Mega kernel: CTAs [0,256) = qks ; [256, 2304) = pv.
// ---------------------------------------------------------------------------
__global__ __launch_bounds__(512, 1) void attn_mega(
    const float* __restrict__ Qf, const float* __restrict__ Kf,
    const float* __restrict__ Vf, const float* __restrict__ mask,
    __half* __restrict__ phi, float* __restrict__ out) {
  extern __shared__ char smem[];
  const uint32_t sbase = smem_to_u32(smem);
  const int bid = blockIdx.x;
  if (bid < 256) {
    qks_part(bid, sbase, smem, Qf, Kf, mask, phi);
  } else {
    pv_part(bid - 256, sbase, phi, Vf, out);
  }
}

// ---------------------------------------------------------------------------
// Launch
// ---------------------------------------------------------------------------
extern "C" void kernel_launch(void* const* d_in, const int* in_sizes, int n_in,
                              void* d_out, int out_size) {
  const float* Q = (const float*)d_in[0];
  const float* K = (const float*)d_in[1];
  const float* V = (const float*)d_in[2];
  const float* mask = (const float*)d_in[3];
  float* out = (float*)d_out;

  __half* phi; int* flag;
  cudaGetSymbolAddress((void**)&phi, g_phi);
  cudaGetSymbolAddress((void**)&flag, g_flag);

  cudaMemsetAsync(flag, 0, HH * sizeof(int));

  cudaFuncSetAttribute(attn_mega, cudaFuncAttributeMaxDynamicSharedMemorySize,
                       MEGA_SMEM);
  attn_mega<<<2304, 512, MEGA_SMEM>>>(Q, K, V, mask, phi, out);
}